// round 1
// baseline (speedup 1.0000x reference)
#include <cuda_runtime.h>
#include <math.h>

// Problem constants (fixed shapes)
//  T=64, B=64, S=64, E=1024, D=1024, G=4*D=4096
// Inputs (metadata order):
//  0 emb[T,B,E] 1 context[S,B,D] 2 input_feed[1,B,D] 3 h0[2,B,D] 4 c0[2,B,D]
//  5 W_ih0[4096,2048] 6 W_hh0[4096,1024] 7 b_ih0 8 b_hh0
//  9 W_ih1[4096,1024] 10 W_hh1[4096,1024] 11 b_ih1 12 b_hh1
//  13 W_in[1024,1024] 14 W_out[1024,2048]
// Output: outputs[T,B,D] then attns[T,B,S] (fp32, concatenated)

// ---------------- device scratch (static; no allocations) ----------------
__device__ float g_embW[64 * 64 * 4096];   // precomputed emb@W_ih0[:, :E]^T + b_ih0 + b_hh0
__device__ float g_Wcat0[4096 * 2048];     // [W_ih0[:,E:] | W_hh0]
__device__ float g_Wcat1[4096 * 2048];     // [W_ih1 | W_hh1]
__device__ float g_part[8 * 64 * 4096];    // split-K partials (reused by all per-step GEMMs)
__device__ float g_Z0[64 * 2048];          // [feed | h0_prev]
__device__ float g_Z1[64 * 2048];          // [h0_new | h1_prev]
__device__ float g_Zo[64 * 2048];          // [cvec | h1_new]
__device__ float g_c0[64 * 1024];
__device__ float g_c1[64 * 1024];
__device__ float g_bias0[4096];            // b_ih0 + b_hh0
__device__ float g_bias1[4096];            // b_ih1 + b_hh1

// ---------------- packed f32x2 helpers ----------------
__device__ __forceinline__ unsigned long long pack2(float x, float y) {
    unsigned long long r;
    asm("mov.b64 %0, {%1, %2};" : "=l"(r) : "f"(x), "f"(y));
    return r;
}
#define FFMA2(d, a, b) asm("fma.rn.f32x2 %0, %1, %2, %0;" : "+l"(d) : "l"(a), "l"(b))

// ---------------- generic tiled GEMM: C[m,n] = sum_k A[m,k] * W[n,k] ----------------
// Block tile: 64 (M) x TN (N). 128 threads, each computes 8m x (TN/16)n via FFMA2
// (M accumulated in packed pairs). gridDim.y = split-K count (K chunks).
// PARTIAL: write partials to out[(ks*64+m)*N + n]. Otherwise: out[(m0+m)*N+n] = acc + bias[n].
template <int TN, bool PARTIAL>
__global__ void __launch_bounds__(128) gemm_f32(
    const float* __restrict__ A, int lda,
    const float* __restrict__ W, int ldw,
    float* __restrict__ out, int N,
    const float* __restrict__ bias, int K)
{
    constexpr int KT = 16;
    constexpr int TNT = TN / 16;
    __shared__ float As[KT][64];
    __shared__ float Bs[KT][TN];

    const int tid = threadIdx.x;
    const int tmg = tid >> 4;     // 0..7  -> rows tmg*8 .. tmg*8+7
    const int tng = tid & 15;     // 0..15 -> cols tng*TNT .. +TNT-1
    const int m0 = blockIdx.z * 64;
    const int n0 = blockIdx.x * TN;
    const int KC = K / gridDim.y;
    const int k0 = blockIdx.y * KC;

    unsigned long long acc[4][TNT];
#pragma unroll
    for (int i = 0; i < 4; i++)
#pragma unroll
        for (int j = 0; j < TNT; j++) acc[i][j] = 0ull;

    for (int kt = 0; kt < KC; kt += KT) {
        // stage A tile: 64 x 16 (store transposed k-major)
#pragma unroll
        for (int r = 0; r < 2; r++) {
            int idx = tid + r * 128;
            int m = idx >> 2, q = idx & 3;
            float4 v = *(const float4*)(A + (size_t)(m0 + m) * lda + (k0 + kt + q * 4));
            As[q * 4 + 0][m] = v.x; As[q * 4 + 1][m] = v.y;
            As[q * 4 + 2][m] = v.z; As[q * 4 + 3][m] = v.w;
        }
        // stage B tile: TN x 16
#pragma unroll
        for (int r = 0; r < TN / 32; r++) {
            int idx = tid + r * 128;
            int n = idx >> 2, q = idx & 3;
            float4 v = *(const float4*)(W + (size_t)(n0 + n) * ldw + (k0 + kt + q * 4));
            Bs[q * 4 + 0][n] = v.x; Bs[q * 4 + 1][n] = v.y;
            Bs[q * 4 + 2][n] = v.z; Bs[q * 4 + 3][n] = v.w;
        }
        __syncthreads();
#pragma unroll
        for (int kk = 0; kk < KT; kk++) {
            unsigned long long av[4];
            const unsigned long long* ap =
                reinterpret_cast<const unsigned long long*>(&As[kk][tmg * 8]);
#pragma unroll
            for (int i = 0; i < 4; i++) av[i] = ap[i];
            unsigned long long bd[TNT];
#pragma unroll
            for (int j = 0; j < TNT; j++) {
                float b = Bs[kk][tng * TNT + j];
                bd[j] = pack2(b, b);
            }
#pragma unroll
            for (int i = 0; i < 4; i++)
#pragma unroll
                for (int j = 0; j < TNT; j++)
                    FFMA2(acc[i][j], av[i], bd[j]);
        }
        __syncthreads();
    }

#pragma unroll
    for (int i = 0; i < 4; i++) {
#pragma unroll
        for (int j = 0; j < TNT; j++) {
            unsigned long long v = acc[i][j];
            float lo = __uint_as_float((unsigned)(v & 0xffffffffull));
            float hi = __uint_as_float((unsigned)(v >> 32));
            int r0 = tmg * 8 + 2 * i;
            int n = n0 + tng * TNT + j;
            if (PARTIAL) {
                size_t base = (size_t)blockIdx.y * 64 * (size_t)N;
                out[base + (size_t)r0 * N + n] = lo;
                out[base + (size_t)(r0 + 1) * N + n] = hi;
            } else {
                float bb = bias ? bias[n] : 0.f;
                out[(size_t)(m0 + r0) * N + n] = lo + bb;
                out[(size_t)(m0 + r0 + 1) * N + n] = hi + bb;
            }
        }
    }
}

// ---------------- LSTM cell: reduce split-K partials + base, apply gates ----------------
// bias_mode 0: base indexed [b*4096+n] (precomputed embW slice). 1: base[n] broadcast bias.
__global__ void lstm_cell(const float* __restrict__ part, int KS,
                          const float* __restrict__ base, int bias_mode,
                          float* __restrict__ c,
                          float* __restrict__ hA, int offA,
                          float* __restrict__ hB, int offB)
{
    int e = blockIdx.x * blockDim.x + threadIdx.x;   // 0..65535
    int b = e >> 10, d = e & 1023;
    float g[4];
#pragma unroll
    for (int j = 0; j < 4; j++) {
        int n = j * 1024 + d;
        float acc = bias_mode ? base[n] : base[(size_t)b * 4096 + n];
        for (int ks = 0; ks < KS; ks++)
            acc += part[((size_t)ks * 64 + b) * 4096 + n];
        g[j] = acc;
    }
    float ig = 1.f / (1.f + expf(-g[0]));
    float fg = 1.f / (1.f + expf(-g[1]));
    float gg = tanhf(g[2]);
    float og = 1.f / (1.f + expf(-g[3]));
    float cn = fg * c[e] + ig * gg;
    float h  = og * tanhf(cn);
    c[e] = cn;
    hA[(size_t)b * 2048 + offA + d] = h;
    hB[(size_t)b * 2048 + offB + d] = h;
}

// ---------------- attention: q-reduce, scores, softmax, context vector ----------------
__global__ void attention_k(const float* __restrict__ part, int KS,
                            const float* __restrict__ ctx,   // [S,B,D]
                            float* __restrict__ attns_t,     // [B,S] slice of output
                            float* __restrict__ zo)          // cvec -> g_Zo[:, 0:1024]
{
    __shared__ float qs[1024];
    __shared__ float sc[64];
    int b = blockIdx.x, tid = threadIdx.x;
    for (int d = tid; d < 1024; d += 256) {
        float acc = 0.f;
        for (int ks = 0; ks < KS; ks++)
            acc += part[((size_t)ks * 64 + b) * 1024 + d];
        qs[d] = acc;
    }
    __syncthreads();
    int w = tid >> 5, lane = tid & 31;
    for (int so = 0; so < 8; so++) {
        int s = w * 8 + so;
        const float* cr = ctx + ((size_t)s * 64 + b) * 1024;
        float acc = 0.f;
        for (int d = lane; d < 1024; d += 32) acc += qs[d] * cr[d];
#pragma unroll
        for (int off = 16; off; off >>= 1) acc += __shfl_down_sync(0xffffffffu, acc, off);
        if (lane == 0) sc[s] = acc;
    }
    __syncthreads();
    if (tid < 32) {
        float v0 = sc[tid], v1 = sc[tid + 32];
        float m = fmaxf(v0, v1);
#pragma unroll
        for (int off = 16; off; off >>= 1) m = fmaxf(m, __shfl_xor_sync(0xffffffffu, m, off));
        float e0 = expf(v0 - m), e1 = expf(v1 - m);
        float s = e0 + e1;
#pragma unroll
        for (int off = 16; off; off >>= 1) s += __shfl_xor_sync(0xffffffffu, s, off);
        float inv = 1.f / s;
        float a0 = e0 * inv, a1 = e1 * inv;
        sc[tid] = a0; sc[tid + 32] = a1;
        attns_t[b * 64 + tid] = a0;
        attns_t[b * 64 + tid + 32] = a1;
    }
    __syncthreads();
    for (int d = tid; d < 1024; d += 256) {
        float acc = 0.f;
#pragma unroll 8
        for (int s = 0; s < 64; s++)
            acc += sc[s] * ctx[((size_t)s * 64 + b) * 1024 + d];
        zo[(size_t)b * 2048 + d] = acc;
    }
}

// ---------------- output tanh + next input feed ----------------
__global__ void attn_out(const float* __restrict__ part, int KS,
                         float* __restrict__ out_t, float* __restrict__ z0)
{
    int e = blockIdx.x * blockDim.x + threadIdx.x;
    int b = e >> 10, d = e & 1023;
    float acc = 0.f;
    for (int ks = 0; ks < KS; ks++)
        acc += part[((size_t)ks * 64 + b) * 1024 + d];
    float h = tanhf(acc);
    out_t[e] = h;
    z0[(size_t)b * 2048 + d] = h;
}

// ---------------- init state + fused biases ----------------
__global__ void init_state(const float* __restrict__ input_feed,
                           const float* __restrict__ h0, const float* __restrict__ c0,
                           const float* __restrict__ b_ih0, const float* __restrict__ b_hh0,
                           const float* __restrict__ b_ih1, const float* __restrict__ b_hh1)
{
    int e = blockIdx.x * blockDim.x + threadIdx.x;   // 65536
    int b = e >> 10, d = e & 1023;
    g_Z0[b * 2048 + d] = input_feed[e];
    g_Z0[b * 2048 + 1024 + d] = h0[e];
    g_Z1[b * 2048 + 1024 + d] = h0[65536 + e];
    g_c0[e] = c0[e];
    g_c1[e] = c0[65536 + e];
    if (e < 4096) {
        g_bias0[e] = b_ih0[e] + b_hh0[e];
        g_bias1[e] = b_ih1[e] + b_hh1[e];
    }
}

// ---------------- pack concatenated recurrent weights ----------------
__global__ void pack_weights(const float* __restrict__ W_ih0, const float* __restrict__ W_hh0,
                             const float* __restrict__ W_ih1, const float* __restrict__ W_hh1)
{
    size_t stride = (size_t)gridDim.x * blockDim.x;
    for (size_t i = (size_t)blockIdx.x * blockDim.x + threadIdx.x;
         i < 4096ull * 2048ull; i += stride) {
        size_t n = i >> 11, k = i & 2047;
        g_Wcat0[i] = (k < 1024) ? W_ih0[n * 2048 + 1024 + k] : W_hh0[n * 1024 + (k - 1024)];
        g_Wcat1[i] = (k < 1024) ? W_ih1[n * 1024 + k]        : W_hh1[n * 1024 + (k - 1024)];
    }
}

// ---------------- host orchestration ----------------
extern "C" void kernel_launch(void* const* d_in, const int* in_sizes, int n_in,
                              void* d_out, int out_size)
{
    (void)in_sizes; (void)n_in; (void)out_size;
    const float* emb        = (const float*)d_in[0];
    const float* context    = (const float*)d_in[1];
    const float* input_feed = (const float*)d_in[2];
    const float* h0         = (const float*)d_in[3];
    const float* c0         = (const float*)d_in[4];
    const float* W_ih0      = (const float*)d_in[5];
    const float* W_hh0      = (const float*)d_in[6];
    const float* b_ih0      = (const float*)d_in[7];
    const float* b_hh0      = (const float*)d_in[8];
    const float* W_ih1      = (const float*)d_in[9];
    const float* W_hh1      = (const float*)d_in[10];
    const float* b_ih1      = (const float*)d_in[11];
    const float* b_hh1      = (const float*)d_in[12];
    const float* W_in       = (const float*)d_in[13];
    const float* W_out      = (const float*)d_in[14];

    float* outs  = (float*)d_out;               // [64,64,1024]
    float* attns = outs + 64 * 64 * 1024;       // [64,64,64]

    float *p_embW, *p_Wcat0, *p_Wcat1, *p_part, *p_Z0, *p_Z1, *p_Zo,
          *p_c0, *p_c1, *p_bias0, *p_bias1;
    cudaGetSymbolAddress((void**)&p_embW,  g_embW);
    cudaGetSymbolAddress((void**)&p_Wcat0, g_Wcat0);
    cudaGetSymbolAddress((void**)&p_Wcat1, g_Wcat1);
    cudaGetSymbolAddress((void**)&p_part,  g_part);
    cudaGetSymbolAddress((void**)&p_Z0,    g_Z0);
    cudaGetSymbolAddress((void**)&p_Z1,    g_Z1);
    cudaGetSymbolAddress((void**)&p_Zo,    g_Zo);
    cudaGetSymbolAddress((void**)&p_c0,    g_c0);
    cudaGetSymbolAddress((void**)&p_c1,    g_c1);
    cudaGetSymbolAddress((void**)&p_bias0, g_bias0);
    cudaGetSymbolAddress((void**)&p_bias1, g_bias1);

    init_state<<<256, 256>>>(input_feed, h0, c0, b_ih0, b_hh0, b_ih1, b_hh1);
    pack_weights<<<2048, 256>>>(W_ih0, W_hh0, W_ih1, W_hh1);
    // Precompute embW[t*64+b, :] = emb[t,b,:] @ W_ih0[:, :E]^T + (b_ih0 + b_hh0)
    gemm_f32<128, false><<<dim3(32, 1, 64), 128>>>(emb, 1024, W_ih0, 2048,
                                                   p_embW, 4096, p_bias0, 1024);

    for (int t = 0; t < 64; t++) {
        // LSTM layer 0: [feed|h0_prev] @ [Wfeed|Whh0]^T  (split-K = 8)
        gemm_f32<128, true><<<dim3(32, 8, 1), 128>>>(p_Z0, 2048, p_Wcat0, 2048,
                                                     p_part, 4096, nullptr, 2048);
        lstm_cell<<<256, 256>>>(p_part, 8, p_embW + (size_t)t * 64 * 4096, 0,
                                p_c0, p_Z1, 0, p_Z0, 1024);
        // LSTM layer 1
        gemm_f32<128, true><<<dim3(32, 8, 1), 128>>>(p_Z1, 2048, p_Wcat1, 2048,
                                                     p_part, 4096, nullptr, 2048);
        lstm_cell<<<256, 256>>>(p_part, 8, p_bias1, 1,
                                p_c1, p_Z1, 1024, p_Zo, 1024);
        // q = h1 @ W_in^T
        gemm_f32<64, true><<<dim3(16, 8, 1), 128>>>(p_Zo + 1024, 2048, W_in, 1024,
                                                    p_part, 1024, nullptr, 1024);
        // attention: scores, softmax -> attns[t], cvec -> Zo first half
        attention_k<<<64, 256>>>(p_part, 8, context, attns + (size_t)t * 64 * 64, p_Zo);
        // attn_h = tanh([cvec|h1] @ W_out^T)
        gemm_f32<64, true><<<dim3(16, 16, 1), 128>>>(p_Zo, 2048, W_out, 2048,
                                                     p_part, 1024, nullptr, 2048);
        attn_out<<<256, 256>>>(p_part, 16, outs + (size_t)t * 64 * 1024, p_Z0);
    }
}

// round 3
// speedup vs baseline: 1.7109x; 1.7109x over previous
#include <cuda_runtime.h>
#include <cuda_bf16.h>
#include <cstdint>
#include <math.h>

// Shapes: T=64, B=64, S=64, E=1024, D=1024, G=4096
// GEMM form: out[n][b] (split-K partials) = sum_k W[n][k] * Z[b][k]
// 3-term hi/lo bf16 via mma.sync.m16n8k16 with fp32 accumulation.

// ---------------- static device scratch ----------------
__device__ __align__(16) __nv_bfloat16 g_W0e_h[4096*1024], g_W0e_l[4096*1024];
__device__ __align__(16) __nv_bfloat16 g_Wc0_h[4096*2048], g_Wc0_l[4096*2048];
__device__ __align__(16) __nv_bfloat16 g_Wc1_h[4096*2048], g_Wc1_l[4096*2048];
__device__ __align__(16) __nv_bfloat16 g_Win_h[1024*1024], g_Win_l[1024*1024];
__device__ __align__(16) __nv_bfloat16 g_Wout_h[1024*2048], g_Wout_l[1024*2048];
__device__ __align__(16) __nv_bfloat16 g_embh[4096*1024],  g_embl[4096*1024];
__device__ __align__(16) float g_embW[64*4096*64];   // [t][n][b]
__device__ __align__(16) float g_part[8*4096*64];    // split-K partials [ks][n][b]
__device__ __align__(16) __nv_bfloat16 g_Z0h[64*2048], g_Z0l[64*2048];
__device__ __align__(16) __nv_bfloat16 g_Z1h[64*2048], g_Z1l[64*2048];
__device__ __align__(16) __nv_bfloat16 g_Zoh[64*2048], g_Zol[64*2048];
__device__ __align__(16) float g_cT0[1024*64], g_cT1[1024*64];
__device__ __align__(16) float g_bias0[4096], g_bias1[4096];

// ---------------- PTX helpers ----------------
__device__ __forceinline__ uint32_t smem_u32(const void* p) {
    uint32_t a;
    asm("{ .reg .u64 t; cvta.to.shared.u64 t, %1; cvt.u32.u64 %0, t; }" : "=r"(a) : "l"(p));
    return a;
}
__device__ __forceinline__ void ldm4(uint32_t* r, uint32_t a) {
    asm volatile("ldmatrix.sync.aligned.m8n8.x4.shared.b16 {%0,%1,%2,%3}, [%4];"
                 : "=r"(r[0]), "=r"(r[1]), "=r"(r[2]), "=r"(r[3]) : "r"(a));
}
__device__ __forceinline__ void mma_bf16(float* c, const uint32_t* a, uint32_t b0, uint32_t b1) {
    asm volatile("mma.sync.aligned.m16n8k16.row.col.f32.bf16.bf16.f32 "
                 "{%0,%1,%2,%3}, {%4,%5,%6,%7}, {%8,%9}, {%0,%1,%2,%3};"
                 : "+f"(c[0]), "+f"(c[1]), "+f"(c[2]), "+f"(c[3])
                 : "r"(a[0]), "r"(a[1]), "r"(a[2]), "r"(a[3]), "r"(b0), "r"(b1));
}
__device__ __forceinline__ void cpa16(uint32_t s, const void* g) {
    asm volatile("cp.async.cg.shared.global [%0], [%1], 16;" :: "r"(s), "l"(g));
}
#define CP_COMMIT() asm volatile("cp.async.commit_group;" ::: "memory")

__device__ __forceinline__ void hilo(float x, __nv_bfloat16& h, __nv_bfloat16& l) {
    h = __float2bfloat16(x);
    l = __float2bfloat16(x - __bfloat162float(h));
}

// ---------------- mma.sync GEMM ----------------
// grid: (Mtiles, KSPLIT, Zbatches), block 256.
// out[((z*KS+ks)*Nrows + n)*64 + b] = sum over CTA's K chunk of W[n][k]*Z[b][k].
static constexpr int PITCH = 72;                    // bf16 elems; 144B rows
static constexpr int WBYTES = 128 * PITCH * 2;      // 18432
static constexpr int ZBYTES = 64 * PITCH * 2;       // 9216
static constexpr int BUFBYTES = 2 * WBYTES + 2 * ZBYTES;  // 55296
static constexpr int GEMM_SMEM = 2 * BUFBYTES;            // 110592

__global__ void __launch_bounds__(256) gemm3(
    const __nv_bfloat16* __restrict__ Wh, const __nv_bfloat16* __restrict__ Wl,
    const __nv_bfloat16* __restrict__ Zh, const __nv_bfloat16* __restrict__ Zl,
    int ldz, float* __restrict__ out, int K)
{
    extern __shared__ __align__(16) char dsm[];
    const int tid  = threadIdx.x;
    const int lane = tid & 31, wid = tid >> 5;
    const int wm = wid >> 1, wn = wid & 1;
    const int Nrows = gridDim.x * 128;
    const int n0 = blockIdx.x * 128;
    const int Kc = K / gridDim.y;
    const int k0 = blockIdx.y * Kc;
    const int chunks = Kc / 64;

    Zh += (size_t)blockIdx.z * 64 * ldz;
    Zl += (size_t)blockIdx.z * 64 * ldz;
    out += (size_t)(blockIdx.z * gridDim.y + blockIdx.y) * Nrows * 64;

    const uint32_t sb = smem_u32(dsm);

    float acc[2][4][4];
#pragma unroll
    for (int mi = 0; mi < 2; mi++)
#pragma unroll
        for (int j = 0; j < 4; j++)
#pragma unroll
            for (int q = 0; q < 4; q++) acc[mi][j][q] = 0.f;

    // ---- stage chunk c into buffer c&1 ----
    auto stage = [&](int c) {
        const uint32_t S = sb + (c & 1) * BUFBYTES;
        const int kb = k0 + c * 64;
#pragma unroll
        for (int i = 0; i < 4; i++) {
            int idx = i * 256 + tid;
            int row = idx >> 3, cg = idx & 7;
            size_t g = (size_t)(n0 + row) * K + kb + cg * 8;
            uint32_t d = S + (row * PITCH + cg * 8) * 2;
            cpa16(d, Wh + g);
            cpa16(d + WBYTES, Wl + g);
        }
#pragma unroll
        for (int i = 0; i < 2; i++) {
            int idx = i * 256 + tid;
            int row = idx >> 3, cg = idx & 7;
            size_t g = (size_t)row * ldz + kb + cg * 8;
            uint32_t d = S + 2 * WBYTES + (row * PITCH + cg * 8) * 2;
            cpa16(d, Zh + g);
            cpa16(d + ZBYTES, Zl + g);
        }
        CP_COMMIT();
    };

    stage(0);
    for (int c = 0; c < chunks; c++) {
        if (c + 1 < chunks) {
            stage(c + 1);
            asm volatile("cp.async.wait_group 1;" ::: "memory");
        } else {
            asm volatile("cp.async.wait_group 0;" ::: "memory");
        }
        __syncthreads();

        const uint32_t S = sb + (c & 1) * BUFBYTES;
        const uint32_t aw = S + ((wm * 32 + (lane & 15)) * PITCH + (lane >> 4) * 8) * 2;
        const uint32_t bz = S + 2 * WBYTES + ((wn * 32 + (lane & 15)) * PITCH + (lane >> 4) * 8) * 2;

#pragma unroll
        for (int ks = 0; ks < 4; ks++) {
            const uint32_t koff = ks * 32;
            uint32_t ah[2][4], al[2][4], bh[2][4], bl[2][4];
#pragma unroll
            for (int mi = 0; mi < 2; mi++) {
                uint32_t a = aw + mi * 16 * PITCH * 2 + koff;
                ldm4(ah[mi], a);
                ldm4(al[mi], a + WBYTES);
            }
#pragma unroll
            for (int bi = 0; bi < 2; bi++) {
                uint32_t a = bz + bi * 16 * PITCH * 2 + koff;
                ldm4(bh[bi], a);
                ldm4(bl[bi], a + ZBYTES);
            }
#pragma unroll
            for (int mi = 0; mi < 2; mi++)
#pragma unroll
                for (int j = 0; j < 4; j++) {
                    int bi = j >> 1, s = j & 1;
                    mma_bf16(acc[mi][j], ah[mi], bh[bi][s], bh[bi][2 + s]);
                    mma_bf16(acc[mi][j], ah[mi], bl[bi][s], bl[bi][2 + s]);
                    mma_bf16(acc[mi][j], al[mi], bh[bi][s], bh[bi][2 + s]);
                }
        }
        __syncthreads();
    }

    // epilogue: C frag (m16n8): c0,c1 -> (row=t>>2, n=(t&3)*2+{0,1}); c2,c3 -> row+8
#pragma unroll
    for (int mi = 0; mi < 2; mi++)
#pragma unroll
        for (int j = 0; j < 4; j++) {
            int m = n0 + wm * 32 + mi * 16 + (lane >> 2);
            int b = wn * 32 + j * 8 + (lane & 3) * 2;
            *(float2*)(out + (size_t)m * 64 + b) =
                make_float2(acc[mi][j][0], acc[mi][j][1]);
            *(float2*)(out + (size_t)(m + 8) * 64 + b) =
                make_float2(acc[mi][j][2], acc[mi][j][3]);
        }
}

// ---------------- LSTM cell: reduce partials, apply gates ----------------
__global__ void lstm_cell(const float* __restrict__ part, int KS,
                          const float* __restrict__ base,   // [n][b] or null
                          const float* __restrict__ bias,   // [4096]
                          float* __restrict__ cT,
                          __nv_bfloat16* hAh, __nv_bfloat16* hAl, int offA,
                          __nv_bfloat16* hBh, __nv_bfloat16* hBl, int offB)
{
    int e = blockIdx.x * blockDim.x + threadIdx.x;   // e = d*64 + b
    int d = e >> 6, b = e & 63;
    float g[4];
#pragma unroll
    for (int j = 0; j < 4; j++) {
        float acc = bias[j * 1024 + d];
        if (base) acc += base[(size_t)j * 65536 + e];
        for (int ks = 0; ks < KS; ks++)
            acc += part[(size_t)ks * 262144 + (size_t)j * 65536 + e];
        g[j] = acc;
    }
    float ig = 1.f / (1.f + expf(-g[0]));
    float fg = 1.f / (1.f + expf(-g[1]));
    float gg = tanhf(g[2]);
    float og = 1.f / (1.f + expf(-g[3]));
    float cn = fg * cT[e] + ig * gg;
    float h  = og * tanhf(cn);
    cT[e] = cn;
    __nv_bfloat16 hh, hl;
    hilo(h, hh, hl);
    hAh[b * 2048 + offA + d] = hh; hAl[b * 2048 + offA + d] = hl;
    hBh[b * 2048 + offB + d] = hh; hBl[b * 2048 + offB + d] = hl;
}

// ---------------- attention ----------------
__global__ void attention_k(const float* __restrict__ part, int KS,
                            const float* __restrict__ ctx,   // [S,B,D]
                            float* __restrict__ attns_t,     // [B,S]
                            __nv_bfloat16* __restrict__ zoh,
                            __nv_bfloat16* __restrict__ zol)
{
    __shared__ float qs[1024];
    __shared__ float sc[64];
    int b = blockIdx.x, tid = threadIdx.x;
    for (int d = tid; d < 1024; d += 256) {
        float acc = 0.f;
        for (int ks = 0; ks < KS; ks++)
            acc += part[((size_t)ks * 1024 + d) * 64 + b];
        qs[d] = acc;
    }
    __syncthreads();
    int w = tid >> 5, lane = tid & 31;
    for (int so = 0; so < 8; so++) {
        int s = w * 8 + so;
        const float* cr = ctx + ((size_t)s * 64 + b) * 1024;
        float acc = 0.f;
        for (int d = lane; d < 1024; d += 32) acc += qs[d] * cr[d];
#pragma unroll
        for (int off = 16; off; off >>= 1) acc += __shfl_down_sync(0xffffffffu, acc, off);
        if (lane == 0) sc[s] = acc;
    }
    __syncthreads();
    if (tid < 32) {
        float v0 = sc[tid], v1 = sc[tid + 32];
        float m = fmaxf(v0, v1);
#pragma unroll
        for (int off = 16; off; off >>= 1) m = fmaxf(m, __shfl_xor_sync(0xffffffffu, m, off));
        float e0 = expf(v0 - m), e1 = expf(v1 - m);
        float s = e0 + e1;
#pragma unroll
        for (int off = 16; off; off >>= 1) s += __shfl_xor_sync(0xffffffffu, s, off);
        float inv = 1.f / s;
        float a0 = e0 * inv, a1 = e1 * inv;
        sc[tid] = a0; sc[tid + 32] = a1;
        attns_t[b * 64 + tid] = a0;
        attns_t[b * 64 + tid + 32] = a1;
    }
    __syncthreads();
    for (int d = tid; d < 1024; d += 256) {
        float acc = 0.f;
#pragma unroll 8
        for (int s = 0; s < 64; s++)
            acc += sc[s] * ctx[((size_t)s * 64 + b) * 1024 + d];
        __nv_bfloat16 hh, hl;
        hilo(acc, hh, hl);
        zoh[b * 2048 + d] = hh;
        zol[b * 2048 + d] = hl;
    }
}

// ---------------- output tanh + next input feed ----------------
__global__ void attn_out(const float* __restrict__ part, int KS,
                         float* __restrict__ out_t,
                         __nv_bfloat16* __restrict__ z0h,
                         __nv_bfloat16* __restrict__ z0l)
{
    int e = blockIdx.x * blockDim.x + threadIdx.x;  // e = d*64 + b
    int d = e >> 6, b = e & 63;
    float acc = 0.f;
    for (int ks = 0; ks < KS; ks++)
        acc += part[(size_t)ks * 65536 + e];
    float h = tanhf(acc);
    out_t[b * 1024 + d] = h;
    __nv_bfloat16 hh, hl;
    hilo(h, hh, hl);
    z0h[b * 2048 + d] = hh;
    z0l[b * 2048 + d] = hl;
}

// ---------------- init state ----------------
__global__ void init_state(const float* __restrict__ input_feed,
                           const float* __restrict__ h0, const float* __restrict__ c0)
{
    int e = blockIdx.x * blockDim.x + threadIdx.x;  // 65536
    int b = e >> 10, d = e & 1023;
    __nv_bfloat16 hh, hl;
    hilo(input_feed[e], hh, hl);
    g_Z0h[b * 2048 + d] = hh; g_Z0l[b * 2048 + d] = hl;
    hilo(h0[e], hh, hl);
    g_Z0h[b * 2048 + 1024 + d] = hh; g_Z0l[b * 2048 + 1024 + d] = hl;
    hilo(h0[65536 + e], hh, hl);
    g_Z1h[b * 2048 + 1024 + d] = hh; g_Z1l[b * 2048 + 1024 + d] = hl;
    g_cT0[d * 64 + b] = c0[e];
    g_cT1[d * 64 + b] = c0[65536 + e];
}

// ---------------- weight prep (hi/lo conversion + packing) ----------------
__global__ void prep_w(const float* __restrict__ W_ih0, const float* __restrict__ W_hh0,
                       const float* __restrict__ W_ih1, const float* __restrict__ W_hh1,
                       const float* __restrict__ W_in,  const float* __restrict__ W_out,
                       const float* __restrict__ emb,
                       const float* __restrict__ b_ih0, const float* __restrict__ b_hh0,
                       const float* __restrict__ b_ih1, const float* __restrict__ b_hh1)
{
    size_t stride = (size_t)gridDim.x * blockDim.x;
    for (size_t i = (size_t)blockIdx.x * blockDim.x + threadIdx.x;
         i < 4096ull * 2048ull; i += stride) {
        size_t n = i >> 11, k = i & 2047;
        float v0 = (k < 1024) ? W_ih0[n * 2048 + 1024 + k] : W_hh0[n * 1024 + (k - 1024)];
        hilo(v0, g_Wc0_h[i], g_Wc0_l[i]);
        float v1 = (k < 1024) ? W_ih1[n * 1024 + k] : W_hh1[n * 1024 + (k - 1024)];
        hilo(v1, g_Wc1_h[i], g_Wc1_l[i]);
        if (n < 1024) hilo(W_out[i], g_Wout_h[i], g_Wout_l[i]);
        if (i < 4096ull * 1024ull) {
            size_t nn = i >> 10, kk = i & 1023;
            hilo(W_ih0[nn * 2048 + kk], g_W0e_h[i], g_W0e_l[i]);
            hilo(emb[i], g_embh[i], g_embl[i]);
        }
        if (i < 1024ull * 1024ull) hilo(W_in[i], g_Win_h[i], g_Win_l[i]);
        if (i < 4096) {
            g_bias0[i] = b_ih0[i] + b_hh0[i];
            g_bias1[i] = b_ih1[i] + b_hh1[i];
        }
    }
}

// ---------------- host orchestration ----------------
extern "C" void kernel_launch(void* const* d_in, const int* in_sizes, int n_in,
                              void* d_out, int out_size)
{
    (void)in_sizes; (void)n_in; (void)out_size;
    const float* emb        = (const float*)d_in[0];
    const float* context    = (const float*)d_in[1];
    const float* input_feed = (const float*)d_in[2];
    const float* h0         = (const float*)d_in[3];
    const float* c0         = (const float*)d_in[4];
    const float* W_ih0      = (const float*)d_in[5];
    const float* W_hh0      = (const float*)d_in[6];
    const float* b_ih0      = (const float*)d_in[7];
    const float* b_hh0      = (const float*)d_in[8];
    const float* W_ih1      = (const float*)d_in[9];
    const float* W_hh1      = (const float*)d_in[10];
    const float* b_ih1      = (const float*)d_in[11];
    const float* b_hh1      = (const float*)d_in[12];
    const float* W_in       = (const float*)d_in[13];
    const float* W_out      = (const float*)d_in[14];

    float* outs  = (float*)d_out;
    float* attns = outs + 64 * 64 * 1024;

    static bool attr_set = false;
    if (!attr_set) {
        cudaFuncSetAttribute(gemm3, cudaFuncAttributeMaxDynamicSharedMemorySize, GEMM_SMEM);
        attr_set = true;
    }

    __nv_bfloat16 *pW0eh, *pW0el, *pWc0h, *pWc0l, *pWc1h, *pWc1l,
                  *pWinh, *pWinl, *pWouth, *pWoutl, *pEh, *pEl,
                  *pZ0h, *pZ0l, *pZ1h, *pZ1l, *pZoh, *pZol;
    float *pEmbW, *pPart, *pC0, *pC1, *pB0, *pB1;
    cudaGetSymbolAddress((void**)&pW0eh, g_W0e_h);  cudaGetSymbolAddress((void**)&pW0el, g_W0e_l);
    cudaGetSymbolAddress((void**)&pWc0h, g_Wc0_h);  cudaGetSymbolAddress((void**)&pWc0l, g_Wc0_l);
    cudaGetSymbolAddress((void**)&pWc1h, g_Wc1_h);  cudaGetSymbolAddress((void**)&pWc1l, g_Wc1_l);
    cudaGetSymbolAddress((void**)&pWinh, g_Win_h);  cudaGetSymbolAddress((void**)&pWinl, g_Win_l);
    cudaGetSymbolAddress((void**)&pWouth, g_Wout_h); cudaGetSymbolAddress((void**)&pWoutl, g_Wout_l);
    cudaGetSymbolAddress((void**)&pEh, g_embh);      cudaGetSymbolAddress((void**)&pEl, g_embl);
    cudaGetSymbolAddress((void**)&pZ0h, g_Z0h);      cudaGetSymbolAddress((void**)&pZ0l, g_Z0l);
    cudaGetSymbolAddress((void**)&pZ1h, g_Z1h);      cudaGetSymbolAddress((void**)&pZ1l, g_Z1l);
    cudaGetSymbolAddress((void**)&pZoh, g_Zoh);      cudaGetSymbolAddress((void**)&pZol, g_Zol);
    cudaGetSymbolAddress((void**)&pEmbW, g_embW);
    cudaGetSymbolAddress((void**)&pPart, g_part);
    cudaGetSymbolAddress((void**)&pC0, g_cT0);       cudaGetSymbolAddress((void**)&pC1, g_cT1);
    cudaGetSymbolAddress((void**)&pB0, g_bias0);     cudaGetSymbolAddress((void**)&pB1, g_bias1);

    prep_w<<<4096, 256>>>(W_ih0, W_hh0, W_ih1, W_hh1, W_in, W_out, emb,
                          b_ih0, b_hh0, b_ih1, b_hh1);
    init_state<<<256, 256>>>(input_feed, h0, c0);
    // embW[t][n][b] = emb_t @ W_ih0[:, :1024]^T
    gemm3<<<dim3(32, 1, 64), 256, GEMM_SMEM>>>(pW0eh, pW0el, pEh, pEl, 1024, pEmbW, 1024);

    for (int t = 0; t < 64; t++) {
        // LSTM layer 0: [feed|h0_prev] @ [Wfeed|Whh0]^T
        gemm3<<<dim3(32, 4, 1), 256, GEMM_SMEM>>>(pWc0h, pWc0l, pZ0h, pZ0l, 2048, pPart, 2048);
        lstm_cell<<<256, 256>>>(pPart, 4, pEmbW + (size_t)t * 4096 * 64, pB0,
                                pC0, pZ1h, pZ1l, 0, pZ0h, pZ0l, 1024);
        // LSTM layer 1
        gemm3<<<dim3(32, 4, 1), 256, GEMM_SMEM>>>(pWc1h, pWc1l, pZ1h, pZ1l, 2048, pPart, 2048);
        lstm_cell<<<256, 256>>>(pPart, 4, nullptr, pB1,
                                pC1, pZoh, pZol, 1024, pZ1h, pZ1l, 1024);
        // q = h1 @ W_in^T
        gemm3<<<dim3(8, 8, 1), 256, GEMM_SMEM>>>(pWinh, pWinl, pZoh + 1024, pZol + 1024,
                                                 2048, pPart, 1024);
        attention_k<<<64, 256>>>(pPart, 8, context, attns + (size_t)t * 64 * 64, pZoh, pZol);
        // attn_h = tanh([cvec|h1] @ W_out^T)
        gemm3<<<dim3(8, 8, 1), 256, GEMM_SMEM>>>(pWouth, pWoutl, pZoh, pZol,
                                                 2048, pPart, 2048);
        attn_out<<<256, 256>>>(pPart, 8, outs + (size_t)t * 64 * 1024, pZ0h, pZ0l);
    }
}